// round 2
// baseline (speedup 1.0000x reference)
#include <cuda_runtime.h>
#include <cstdint>
#include <math.h>
#include <float.h>

#define Lq 512
#define Bq 8
#define Nq 32
#define Dq 256
#define GHq 128
#define AHq 64

// Pre-transposed weights (device scratch; static globals are allowed, cudaMalloc is not)
__device__ float g_gw1T[2 * Dq * GHq];  // [512][128] : gw1T[k][n] = gw1[n][k]
__device__ float g_aw1T[Dq * AHq];      // [256][64]  : aw1T[k][n] = aw1[n][k]
__device__ int g_mask_mode;             // 0 = 1-byte bool, 1 = int32, 2 = float32

__global__ void prep_transpose(const float* __restrict__ gw1, const float* __restrict__ aw1,
                               const unsigned char* __restrict__ mask_raw) {
    int i = blockIdx.x * blockDim.x + threadIdx.x;
    if (i < 2 * Dq * GHq) {
        int k = i >> 7, n = i & 127;
        g_gw1T[i] = gw1[n * (2 * Dq) + k];
    }
    if (i < Dq * AHq) {
        int k = i >> 6, n = i & 63;
        g_aw1T[i] = aw1[n * Dq + k];
    }
    // Sniff the mask dtype. First 4096 bytes are in-bounds for every candidate
    // dtype (element count 131072). float32 1.0f has bytes {00,00,80,3F}; int32
    // 0/1 has zero bytes at offsets i%4!=0; bool has 0/1 bytes everywhere.
    if (blockIdx.x == 0 && threadIdx.x == 0) {
        bool anyFloatSig = false, anyOffNonzero = false;
        for (int j = 0; j < 4096; j++) {
            unsigned char c = mask_raw[j];
            if ((j & 3) != 0) {
                if (c == 0x3Fu || c == 0x80u) anyFloatSig = true;
                if (c != 0) anyOffNonzero = true;
            }
        }
        g_mask_mode = anyFloatSig ? 2 : (anyOffNonzero ? 0 : 1);
    }
}

// ---- packed f32x2 helpers (Blackwell sm_103a) ----
__device__ __forceinline__ unsigned long long pack_dup(float x) {
    unsigned long long r;
    asm("mov.b64 %0, {%1, %1};" : "=l"(r) : "f"(x));
    return r;
}
__device__ __forceinline__ unsigned long long pack2(float a, float b) {
    unsigned long long r;
    asm("mov.b64 %0, {%1, %2};" : "=l"(r) : "f"(a), "f"(b));
    return r;
}
__device__ __forceinline__ void fma2(unsigned long long& d, unsigned long long a, unsigned long long b) {
    asm("fma.rn.f32x2 %0, %1, %2, %0;" : "+l"(d) : "l"(a), "l"(b));
}
__device__ __forceinline__ float2 unpack2(unsigned long long v) {
    float2 f;
    asm("mov.b64 {%0, %1}, %2;" : "=f"(f.x), "=f"(f.y) : "l"(v));
    return f;
}

// One CTA per (l, b): 32 messages x 256 dims. Fuses gate MLP, per_msg blend,
// scorer MLP, masked softmax over the 32 messages, and the weighted sum.
__global__ __launch_bounds__(256, 2)
void fusion_main(const float* __restrict__ vert, const float* __restrict__ horiz,
                 const unsigned char* __restrict__ mask,
                 const float* __restrict__ gb1, const float* __restrict__ gw2,
                 const float* __restrict__ gb2,
                 const float* __restrict__ ab1, const float* __restrict__ aw2,
                 const float* __restrict__ ab2,
                 float* __restrict__ out_fused, float* __restrict__ out_pm,
                 float* __restrict__ out_attn) {
    extern __shared__ float smem[];
    float* Vs = smem;                    // [32][256]
    float* Hs = smem + Nq * Dq;          // [32][256]
    float* Ps = smem + 2 * Nq * Dq;      // [32][256] per_msg
    float* logit_s = smem + 3 * Nq * Dq; // [32]
    float* attn_s = logit_s + Nq;        // [32]

    const int lb = blockIdx.x;           // = l*B + b
    const int l = lb / Bq;
    const int b = lb % Bq;
    const int tid = threadIdx.x;

    // ---- stage inputs (contiguous 32 KB each) ----
    const float4* vin = (const float4*)(vert + (size_t)lb * Nq * Dq);
    const float4* hin = (const float4*)(horiz + (size_t)lb * Nq * Dq);
#pragma unroll
    for (int i = tid; i < Nq * Dq / 4; i += 256) {
        ((float4*)Vs)[i] = vin[i];
        ((float4*)Hs)[i] = hin[i];
    }
    __syncthreads();

    // ---- GEMM1: H[32][128] = [V|H] @ gw1^T  (thread tile 4m x 4n, f32x2 accum) ----
    const int tn = tid & 31;   // n base = tn*4
    const int tm = tid >> 5;   // m base = tm*4  (warp owns 4 full m rows)
    unsigned long long acc[4][2];
#pragma unroll
    for (int i = 0; i < 4; i++) { acc[i][0] = 0ull; acc[i][1] = 0ull; }

#pragma unroll 1
    for (int half = 0; half < 2; half++) {
        const float* X = half ? Hs : Vs;
        const float* WT = g_gw1T + half * Dq * GHq;
#pragma unroll 2
        for (int k0 = 0; k0 < Dq; k0 += 4) {
            float xr[4][4];
#pragma unroll
            for (int i = 0; i < 4; i++) {
                float4 t = *(const float4*)&X[(tm * 4 + i) * Dq + k0];
                xr[i][0] = t.x; xr[i][1] = t.y; xr[i][2] = t.z; xr[i][3] = t.w;
            }
#pragma unroll
            for (int j = 0; j < 4; j++) {
                float4 w = __ldg((const float4*)&WT[(size_t)(k0 + j) * GHq + tn * 4]);
                unsigned long long w01 = pack2(w.x, w.y);
                unsigned long long w23 = pack2(w.z, w.w);
#pragma unroll
                for (int i = 0; i < 4; i++) {
                    unsigned long long xx = pack_dup(xr[i][j]);
                    fma2(acc[i][0], xx, w01);
                    fma2(acc[i][1], xx, w23);
                }
            }
        }
    }

    // ---- gate: relu, dot with gw2, warp reduce over n (32 lanes x 4n = 128) ----
    float4 gb1v = __ldg((const float4*)&gb1[tn * 4]);
    float4 gw2v = __ldg((const float4*)&gw2[tn * 4]);
    const float gb2_0 = __ldg(gb2);
    float gate[4];
#pragma unroll
    for (int i = 0; i < 4; i++) {
        float2 p0 = unpack2(acc[i][0]);
        float2 p1 = unpack2(acc[i][1]);
        float h0 = fmaxf(p0.x + gb1v.x, 0.f);
        float h1 = fmaxf(p0.y + gb1v.y, 0.f);
        float h2 = fmaxf(p1.x + gb1v.z, 0.f);
        float h3 = fmaxf(p1.y + gb1v.w, 0.f);
        float gp = h0 * gw2v.x + h1 * gw2v.y + h2 * gw2v.z + h3 * gw2v.w;
#pragma unroll
        for (int off = 16; off >= 1; off >>= 1)
            gp += __shfl_xor_sync(0xffffffffu, gp, off);
        gate[i] = 1.f / (1.f + __expf(-(gp + gb2_0)));
    }

    // ---- per_msg = g*v + (1-g)*h : write to SMEM + GMEM output ----
    float* pm_out = out_pm + (size_t)lb * Nq * Dq;
#pragma unroll
    for (int i = 0; i < 4; i++) {
        int m = tm * 4 + i;
        float g = gate[i];
        float og = 1.f - g;
#pragma unroll
        for (int d = tn * 4; d < Dq; d += 128) {
            float4 v = *(const float4*)&Vs[m * Dq + d];
            float4 hh = *(const float4*)&Hs[m * Dq + d];
            float4 p;
            p.x = fmaf(g, v.x, og * hh.x);
            p.y = fmaf(g, v.y, og * hh.y);
            p.z = fmaf(g, v.z, og * hh.z);
            p.w = fmaf(g, v.w, og * hh.w);
            *(float4*)&Ps[m * Dq + d] = p;
            *(float4*)&pm_out[(size_t)m * Dq + d] = p;
        }
    }
    __syncthreads();

    // ---- GEMM2: A[32][64] = tanh(P @ aw1^T + ab1); logits = A @ aw2^T + ab2 ----
    const int tn2 = tid & 15;  // n base = tn2*4 (covers 64)
    const int tm2 = tid >> 4;  // 0..15, m = 2*tm2 + {0,1}
    unsigned long long acc2[2][2];
#pragma unroll
    for (int i = 0; i < 2; i++) { acc2[i][0] = 0ull; acc2[i][1] = 0ull; }

#pragma unroll 2
    for (int k0 = 0; k0 < Dq; k0 += 4) {
        float xr[2][4];
#pragma unroll
        for (int i = 0; i < 2; i++) {
            float4 t = *(const float4*)&Ps[(tm2 * 2 + i) * Dq + k0];
            xr[i][0] = t.x; xr[i][1] = t.y; xr[i][2] = t.z; xr[i][3] = t.w;
        }
#pragma unroll
        for (int j = 0; j < 4; j++) {
            float4 w = __ldg((const float4*)&g_aw1T[(size_t)(k0 + j) * AHq + tn2 * 4]);
            unsigned long long w01 = pack2(w.x, w.y);
            unsigned long long w23 = pack2(w.z, w.w);
#pragma unroll
            for (int i = 0; i < 2; i++) {
                unsigned long long xx = pack_dup(xr[i][j]);
                fma2(acc2[i][0], xx, w01);
                fma2(acc2[i][1], xx, w23);
            }
        }
    }

    {
        float4 ab1v = __ldg((const float4*)&ab1[tn2 * 4]);
        float4 aw2v = __ldg((const float4*)&aw2[tn2 * 4]);
        const float ab2_0 = __ldg(ab2);
        float lg[2];
#pragma unroll
        for (int i = 0; i < 2; i++) {
            float2 p0 = unpack2(acc2[i][0]);
            float2 p1 = unpack2(acc2[i][1]);
            float a0 = tanhf(p0.x + ab1v.x);
            float a1 = tanhf(p0.y + ab1v.y);
            float a2 = tanhf(p1.x + ab1v.z);
            float a3 = tanhf(p1.y + ab1v.w);
            float lp = a0 * aw2v.x + a1 * aw2v.y + a2 * aw2v.z + a3 * aw2v.w;
#pragma unroll
            for (int off = 8; off >= 1; off >>= 1)
                lp += __shfl_xor_sync(0xffffffffu, lp, off);  // reduces within 16-lane group
            lg[i] = lp + ab2_0;
        }
        if (tn2 == 0) {
            logit_s[tm2 * 2] = lg[0];
            logit_s[tm2 * 2 + 1] = lg[1];
        }
    }
    __syncthreads();

    // ---- masked softmax over the 32 messages (warp 0) ----
    if (tid < 32) {
        float lgv = logit_s[tid];
        size_t midx = ((size_t)b * Nq + tid) * Lq + l;
        int mode = g_mask_mode;
        bool valid;
        if (mode == 2)      valid = ((const float*)mask)[midx] != 0.0f;
        else if (mode == 1) valid = ((const int*)mask)[midx] != 0;
        else                valid = mask[midx] != 0;
        float mv = valid ? lgv : -FLT_MAX;
#pragma unroll
        for (int off = 16; off >= 1; off >>= 1)
            mv = fmaxf(mv, __shfl_xor_sync(0xffffffffu, mv, off));
        float e = valid ? __expf(lgv - mv) : 0.f;
        float s = e;
#pragma unroll
        for (int off = 16; off >= 1; off >>= 1)
            s += __shfl_xor_sync(0xffffffffu, s, off);
        float a = (s > 0.f) ? e / s : 0.f;  // fully-masked rows -> 0 (nan_to_num)
        attn_s[tid] = a;
        out_attn[((size_t)b * Lq + l) * Nq + tid] = a;
    }
    __syncthreads();

    // ---- fused[l][b][d] = sum_m attn[m] * per_msg[m][d] ----
    {
        float f = 0.f;
        int d = tid;  // 256 threads == D
#pragma unroll
        for (int m = 0; m < Nq; m++)
            f = fmaf(attn_s[m], Ps[m * Dq + d], f);
        out_fused[(size_t)lb * Dq + d] = f;
    }
}

extern "C" void kernel_launch(void* const* d_in, const int* in_sizes, int n_in,
                              void* d_out, int out_size) {
    const float* vert = (const float*)d_in[0];
    const float* horiz = (const float*)d_in[1];
    const unsigned char* mask = (const unsigned char*)d_in[2];
    const float* gw1 = (const float*)d_in[3];
    const float* gb1 = (const float*)d_in[4];
    const float* gw2 = (const float*)d_in[5];
    const float* gb2 = (const float*)d_in[6];
    const float* aw1 = (const float*)d_in[7];
    const float* ab1 = (const float*)d_in[8];
    const float* aw2 = (const float*)d_in[9];
    const float* ab2 = (const float*)d_in[10];

    float* out = (float*)d_out;
    float* out_fused = out;                                   // L*B*D
    float* out_pm = out + (size_t)Lq * Bq * Dq;               // L*B*N*D
    float* out_attn = out_pm + (size_t)Lq * Bq * Nq * Dq;     // B*L*N

    prep_transpose<<<(2 * Dq * GHq + 255) / 256, 256>>>(gw1, aw1, mask);

    int smemBytes = (3 * Nq * Dq + 2 * Nq + 16) * (int)sizeof(float);
    cudaFuncSetAttribute(fusion_main, cudaFuncAttributeMaxDynamicSharedMemorySize, smemBytes);
    fusion_main<<<Lq * Bq, 256, smemBytes>>>(vert, horiz, mask,
                                             gb1, gw2, gb2, ab1, aw2, ab2,
                                             out_fused, out_pm, out_attn);
}

// round 3
// speedup vs baseline: 1.1986x; 1.1986x over previous
#include <cuda_runtime.h>
#include <cuda_bf16.h>
#include <cstdint>
#include <math.h>
#include <float.h>

#define Lq 512
#define Bq 8
#define Nq 32
#define Dq 256
#define GHq 128
#define AHq 64
#define KC 512          // concat K for GEMM1
#define CHUNK 64        // K-chunk staged per iteration
#define THREADS 512

// Split weights, bf16 hi/lo (prep kernel fills). Layout [n][k], k contiguous.
__device__ __nv_bfloat16 g_w1hi[GHq * KC];
__device__ __nv_bfloat16 g_w1lo[GHq * KC];
__device__ __nv_bfloat16 g_w2hi[AHq * Dq];
__device__ __nv_bfloat16 g_w2lo[AHq * Dq];
__device__ int g_mask_mode;  // 0 = byte bool, 1 = int32, 2 = float32

__global__ void prep_kernel(const float* __restrict__ gw1, const float* __restrict__ aw1,
                            const unsigned char* __restrict__ mask_raw) {
    int i = blockIdx.x * blockDim.x + threadIdx.x;
    if (i < GHq * KC) {
        float x = gw1[i];  // gw1 is [128][512] row-major already n-major
        __nv_bfloat16 h = __float2bfloat16_rn(x);
        g_w1hi[i] = h;
        g_w1lo[i] = __float2bfloat16_rn(x - __bfloat162float(h));
    }
    if (i < AHq * Dq) {
        float x = aw1[i];  // [64][256]
        __nv_bfloat16 h = __float2bfloat16_rn(x);
        g_w2hi[i] = h;
        g_w2lo[i] = __float2bfloat16_rn(x - __bfloat162float(h));
    }
    if (blockIdx.x == 0 && threadIdx.x == 0) {
        bool anyFloatSig = false, anyOffNonzero = false;
        for (int j = 0; j < 4096; j++) {
            unsigned char c = mask_raw[j];
            if ((j & 3) != 0) {
                if (c == 0x3Fu || c == 0x80u) anyFloatSig = true;
                if (c != 0) anyOffNonzero = true;
            }
        }
        g_mask_mode = anyFloatSig ? 2 : (anyOffNonzero ? 0 : 1);
    }
}

__device__ __forceinline__ uint32_t smem_u32(const void* p) {
    return (uint32_t)__cvta_generic_to_shared(p);
}
__device__ __forceinline__ void ldmatrix_x4(uint32_t* r, uint32_t addr) {
    asm volatile("ldmatrix.sync.aligned.m8n8.x4.shared.b16 {%0,%1,%2,%3}, [%4];"
                 : "=r"(r[0]), "=r"(r[1]), "=r"(r[2]), "=r"(r[3]) : "r"(addr));
}
__device__ __forceinline__ void mma16816(float* c, const uint32_t* a, uint32_t b0, uint32_t b1) {
    asm volatile("mma.sync.aligned.m16n8k16.row.col.f32.bf16.bf16.f32 "
                 "{%0,%1,%2,%3},{%4,%5,%6,%7},{%8,%9},{%0,%1,%2,%3};"
                 : "+f"(c[0]), "+f"(c[1]), "+f"(c[2]), "+f"(c[3])
                 : "r"(a[0]), "r"(a[1]), "r"(a[2]), "r"(a[3]), "r"(b0), "r"(b1));
}

// SMEM layout (bytes)
#define A_STRIDE 72      // bf16 elements per row (64 + 8 pad): bank-conflict-free ldmatrix
#define P_STRIDE 264     // bf16 elements per row (256 + 8 pad)
#define OFF_AHI 0
#define OFF_ALO (128 * A_STRIDE * 2)
#define OFF_PHI (OFF_ALO + 128 * A_STRIDE * 2)
#define OFF_PLO (OFF_PHI + 128 * P_STRIDE * 2)
#define OFF_GPART (OFF_PLO + 128 * P_STRIDE * 2)      // float [128][4]
#define OFF_GATE (OFF_GPART + 128 * 4 * 4)            // float [128]
#define OFF_ATTN (OFF_GATE + 128 * 4)                 // float [128]
#define SMEM_TOTAL (OFF_ATTN + 128 * 4)

__global__ __launch_bounds__(THREADS, 1)
void fusion_main(const float* __restrict__ vert, const float* __restrict__ horiz,
                 const unsigned char* __restrict__ mask,
                 const float* __restrict__ gb1, const float* __restrict__ gw2,
                 const float* __restrict__ gb2,
                 const float* __restrict__ ab1, const float* __restrict__ aw2,
                 const float* __restrict__ ab2,
                 float* __restrict__ out_fused, float* __restrict__ out_pm,
                 float* __restrict__ out_attn) {
    extern __shared__ char smem[];
    __nv_bfloat16* Ahi = (__nv_bfloat16*)(smem + OFF_AHI);
    __nv_bfloat16* Alo = (__nv_bfloat16*)(smem + OFF_ALO);
    __nv_bfloat16* Phi = (__nv_bfloat16*)(smem + OFF_PHI);
    __nv_bfloat16* Plo = (__nv_bfloat16*)(smem + OFF_PLO);
    float* gpart = (float*)(smem + OFF_GPART);
    float* gate_s = (float*)(smem + OFF_GATE);
    float* attn_s = (float*)(smem + OFF_ATTN);

    const int tid = threadIdx.x;
    const int wid = tid >> 5;
    const int lane = tid & 31;
    const int cta = blockIdx.x;          // 4 lb pairs: lb = cta*4 + lbi

    // warp tiles: GEMM1: m32 x n32, 4x4 warp grid
    const int mg = wid >> 2;             // m0 = mg*32
    const int ng = wid & 3;              // n0 = ng*32

    // ldmatrix per-lane addressing within an m16 x k16 tile
    const int lgrp = lane >> 3;
    const int lrow = (lane & 7) + (lgrp & 1) * 8;   // row within m16
    const int lcol = (lgrp >> 1) * 8;               // bf16 col offset within k16

    // ================= GEMM1: C1[128][128] = concat(V,H) @ gw1^T =================
    float acc[2][4][4];
#pragma unroll
    for (int a = 0; a < 2; a++)
#pragma unroll
        for (int b = 0; b < 4; b++)
#pragma unroll
            for (int c = 0; c < 4; c++) acc[a][b][c] = 0.f;

    for (int chunk = 0; chunk < 8; chunk++) {
        const float* feat = (chunk < 4) ? vert : horiz;
        const int kb = (chunk & 3) * CHUNK;          // offset within D
        __syncthreads();
        // stage chunk: 128 m x 64 k fp32 -> bf16 hi/lo
        const float4* src = (const float4*)(feat + (size_t)cta * 128 * Dq);
#pragma unroll
        for (int t = 0; t < 4; t++) {
            int j = tid + t * THREADS;               // 0..2047
            int m = j >> 4;
            int kq = (j & 15) * 4;
            float4 v = src[m * (Dq / 4) + (kb + kq) / 4];
            __nv_bfloat16 h0 = __float2bfloat16_rn(v.x);
            __nv_bfloat16 h1 = __float2bfloat16_rn(v.y);
            __nv_bfloat16 h2 = __float2bfloat16_rn(v.z);
            __nv_bfloat16 h3 = __float2bfloat16_rn(v.w);
            __nv_bfloat16 l0 = __float2bfloat16_rn(v.x - __bfloat162float(h0));
            __nv_bfloat16 l1 = __float2bfloat16_rn(v.y - __bfloat162float(h1));
            __nv_bfloat16 l2 = __float2bfloat16_rn(v.z - __bfloat162float(h2));
            __nv_bfloat16 l3 = __float2bfloat16_rn(v.w - __bfloat162float(h3));
            __nv_bfloat162* dh = (__nv_bfloat162*)&Ahi[m * A_STRIDE + kq];
            dh[0] = __nv_bfloat162(h0, h1);
            dh[1] = __nv_bfloat162(h2, h3);
            __nv_bfloat162* dl = (__nv_bfloat162*)&Alo[m * A_STRIDE + kq];
            dl[0] = __nv_bfloat162(l0, l1);
            dl[1] = __nv_bfloat162(l2, l3);
        }
        __syncthreads();

#pragma unroll
        for (int ks = 0; ks < 4; ks++) {
            const int kk = ks * 16;
            uint32_t ah[2][4], al[2][4];
#pragma unroll
            for (int mt = 0; mt < 2; mt++) {
                int row = mg * 32 + mt * 16 + lrow;
                ldmatrix_x4(ah[mt], smem_u32(&Ahi[row * A_STRIDE + kk + lcol]));
                ldmatrix_x4(al[mt], smem_u32(&Alo[row * A_STRIDE + kk + lcol]));
            }
            const int kglob = chunk * CHUNK + kk + 2 * (lane & 3);
#pragma unroll
            for (int nf = 0; nf < 4; nf++) {
                int n = ng * 32 + nf * 8 + (lane >> 2);
                uint32_t bh0 = *(const uint32_t*)&g_w1hi[n * KC + kglob];
                uint32_t bh1 = *(const uint32_t*)&g_w1hi[n * KC + kglob + 8];
                uint32_t bl0 = *(const uint32_t*)&g_w1lo[n * KC + kglob];
                uint32_t bl1 = *(const uint32_t*)&g_w1lo[n * KC + kglob + 8];
#pragma unroll
                for (int mt = 0; mt < 2; mt++) {
                    mma16816(acc[mt][nf], ah[mt], bh0, bh1);
                    mma16816(acc[mt][nf], al[mt], bh0, bh1);
                    mma16816(acc[mt][nf], ah[mt], bl0, bl1);
                }
            }
        }
    }

    // ---- gate epilogue: relu(C1+gb1) . gw2 per row -> sigmoid ----
    {
        float p0[2] = {0.f, 0.f}, p1[2] = {0.f, 0.f};   // [mt] row-lo / row-hi partials
#pragma unroll
        for (int nf = 0; nf < 4; nf++) {
#pragma unroll
            for (int j = 0; j < 2; j++) {
                int n = ng * 32 + nf * 8 + 2 * (lane & 3) + j;
                float b1v = __ldg(&gb1[n]);
                float w2v = __ldg(&gw2[n]);
#pragma unroll
                for (int mt = 0; mt < 2; mt++) {
                    p0[mt] += fmaxf(acc[mt][nf][j] + b1v, 0.f) * w2v;
                    p1[mt] += fmaxf(acc[mt][nf][j + 2] + b1v, 0.f) * w2v;
                }
            }
        }
#pragma unroll
        for (int o = 1; o <= 2; o <<= 1) {
#pragma unroll
            for (int mt = 0; mt < 2; mt++) {
                p0[mt] += __shfl_xor_sync(0xffffffffu, p0[mt], o);
                p1[mt] += __shfl_xor_sync(0xffffffffu, p1[mt], o);
            }
        }
        if ((lane & 3) == 0) {
            int r = lane >> 2;
#pragma unroll
            for (int mt = 0; mt < 2; mt++) {
                gpart[(mg * 32 + mt * 16 + r) * 4 + ng] = p0[mt];
                gpart[(mg * 32 + mt * 16 + 8 + r) * 4 + ng] = p1[mt];
            }
        }
        __syncthreads();
        if (tid < 128) {
            float s = gpart[tid * 4] + gpart[tid * 4 + 1] + gpart[tid * 4 + 2] + gpart[tid * 4 + 3];
            s += __ldg(gb2);
            gate_s[tid] = 1.f / (1.f + __expf(-s));
        }
        __syncthreads();
    }

    // ---- blend: per_msg = g*v + (1-g)*h (exact fp32 from gmem); stage P hi/lo ----
    {
        const float4* v4 = (const float4*)(vert + (size_t)cta * 128 * Dq);
        const float4* h4 = (const float4*)(horiz + (size_t)cta * 128 * Dq);
        float4* pm4 = (float4*)(out_pm + (size_t)cta * 128 * Dq);
#pragma unroll
        for (int t = 0; t < 16; t++) {
            int j = tid + t * THREADS;       // 0..8191 float4s
            int m = j >> 6;
            int q = (j & 63) * 4;
            float g = gate_s[m];
            float og = 1.f - g;
            float4 v = v4[j];
            float4 h = h4[j];
            float4 p;
            p.x = fmaf(g, v.x, og * h.x);
            p.y = fmaf(g, v.y, og * h.y);
            p.z = fmaf(g, v.z, og * h.z);
            p.w = fmaf(g, v.w, og * h.w);
            pm4[j] = p;
            __nv_bfloat16 h0 = __float2bfloat16_rn(p.x);
            __nv_bfloat16 h1 = __float2bfloat16_rn(p.y);
            __nv_bfloat16 h2 = __float2bfloat16_rn(p.z);
            __nv_bfloat16 h3 = __float2bfloat16_rn(p.w);
            __nv_bfloat16 l0 = __float2bfloat16_rn(p.x - __bfloat162float(h0));
            __nv_bfloat16 l1 = __float2bfloat16_rn(p.y - __bfloat162float(h1));
            __nv_bfloat16 l2 = __float2bfloat16_rn(p.z - __bfloat162float(h2));
            __nv_bfloat16 l3 = __float2bfloat16_rn(p.w - __bfloat162float(h3));
            __nv_bfloat162* dh = (__nv_bfloat162*)&Phi[m * P_STRIDE + q];
            dh[0] = __nv_bfloat162(h0, h1);
            dh[1] = __nv_bfloat162(h2, h3);
            __nv_bfloat162* dl = (__nv_bfloat162*)&Plo[m * P_STRIDE + q];
            dl[0] = __nv_bfloat162(l0, l1);
            dl[1] = __nv_bfloat162(l2, l3);
        }
        __syncthreads();
    }

    // ================= GEMM2: C2[128][64] = P @ aw1^T; logits; softmax ============
    {
        const int ng2 = wid & 3;           // n0 = ng2*16, 4x4 warp grid (m32 x n16)
        float acc2[2][2][4];
#pragma unroll
        for (int a = 0; a < 2; a++)
#pragma unroll
            for (int b = 0; b < 2; b++)
#pragma unroll
                for (int c = 0; c < 4; c++) acc2[a][b][c] = 0.f;

#pragma unroll 1
        for (int ks = 0; ks < 16; ks++) {
            const int kk = ks * 16;
            uint32_t ah[2][4], al[2][4];
#pragma unroll
            for (int mt = 0; mt < 2; mt++) {
                int row = mg * 32 + mt * 16 + lrow;
                ldmatrix_x4(ah[mt], smem_u32(&Phi[row * P_STRIDE + kk + lcol]));
                ldmatrix_x4(al[mt], smem_u32(&Plo[row * P_STRIDE + kk + lcol]));
            }
            const int kg = kk + 2 * (lane & 3);
#pragma unroll
            for (int nf = 0; nf < 2; nf++) {
                int n = ng2 * 16 + nf * 8 + (lane >> 2);
                uint32_t bh0 = *(const uint32_t*)&g_w2hi[n * Dq + kg];
                uint32_t bh1 = *(const uint32_t*)&g_w2hi[n * Dq + kg + 8];
                uint32_t bl0 = *(const uint32_t*)&g_w2lo[n * Dq + kg];
                uint32_t bl1 = *(const uint32_t*)&g_w2lo[n * Dq + kg + 8];
#pragma unroll
                for (int mt = 0; mt < 2; mt++) {
                    mma16816(acc2[mt][nf], ah[mt], bh0, bh1);
                    mma16816(acc2[mt][nf], al[mt], bh0, bh1);
                    mma16816(acc2[mt][nf], ah[mt], bl0, bl1);
                }
            }
        }

        // logits partials: tanh(C2+ab1) . aw2
        float p0[2] = {0.f, 0.f}, p1[2] = {0.f, 0.f};
#pragma unroll
        for (int nf = 0; nf < 2; nf++) {
#pragma unroll
            for (int j = 0; j < 2; j++) {
                int n = ng2 * 16 + nf * 8 + 2 * (lane & 3) + j;
                float b1v = __ldg(&ab1[n]);
                float w2v = __ldg(&aw2[n]);
#pragma unroll
                for (int mt = 0; mt < 2; mt++) {
                    p0[mt] += tanhf(acc2[mt][nf][j] + b1v) * w2v;
                    p1[mt] += tanhf(acc2[mt][nf][j + 2] + b1v) * w2v;
                }
            }
        }
#pragma unroll
        for (int o = 1; o <= 2; o <<= 1) {
#pragma unroll
            for (int mt = 0; mt < 2; mt++) {
                p0[mt] += __shfl_xor_sync(0xffffffffu, p0[mt], o);
                p1[mt] += __shfl_xor_sync(0xffffffffu, p1[mt], o);
            }
        }
        if ((lane & 3) == 0) {
            int r = lane >> 2;
#pragma unroll
            for (int mt = 0; mt < 2; mt++) {
                gpart[(mg * 32 + mt * 16 + r) * 4 + ng2] = p0[mt];
                gpart[(mg * 32 + mt * 16 + 8 + r) * 4 + ng2] = p1[mt];
            }
        }
        __syncthreads();
    }

    // ---- masked softmax per lb (warps 0-3; lane = msg) ----
    if (tid < 128) {
        int lbi = wid;                      // 0..3
        int msg = lane;
        int lb = cta * 4 + lbi;
        int l = lb >> 3, b = lb & 7;
        float lg = gpart[tid * 4] + gpart[tid * 4 + 1] + gpart[tid * 4 + 2] + gpart[tid * 4 + 3];
        lg += __ldg(ab2);
        size_t midx = ((size_t)b * Nq + msg) * Lq + l;
        int mode = g_mask_mode;
        bool valid;
        if (mode == 2)      valid = ((const float*)mask)[midx] != 0.0f;
        else if (mode == 1) valid = ((const int*)mask)[midx] != 0;
        else                valid = mask[midx] != 0;
        float mv = valid ? lg : -FLT_MAX;
#pragma unroll
        for (int o = 16; o >= 1; o >>= 1)
            mv = fmaxf(mv, __shfl_xor_sync(0xffffffffu, mv, o));
        float e = valid ? __expf(lg - mv) : 0.f;
        float s = e;
#pragma unroll
        for (int o = 16; o >= 1; o >>= 1)
            s += __shfl_xor_sync(0xffffffffu, s, o);
        float a = (s > 0.f) ? e / s : 0.f;
        attn_s[tid] = a;
        out_attn[((size_t)b * Lq + l) * Nq + msg] = a;
    }
    __syncthreads();

    // ---- fused[lb][d] = sum_m attn * per_msg (P reconstructed hi+lo) ----
#pragma unroll
    for (int t = 0; t < 2; t++) {
        int j = tid + t * THREADS;          // 0..1023 = 4 lb x 256 d
        int lbi = j >> 8;
        int d = j & 255;
        float f = 0.f;
#pragma unroll
        for (int m = 0; m < Nq; m++) {
            int row = lbi * 32 + m;
            float pv = __bfloat162float(Phi[row * P_STRIDE + d]) +
                       __bfloat162float(Plo[row * P_STRIDE + d]);
            f = fmaf(attn_s[lbi * 32 + m], pv, f);
        }
        out_fused[(size_t)cta * 1024 + j] = f;
    }
}

extern "C" void kernel_launch(void* const* d_in, const int* in_sizes, int n_in,
                              void* d_out, int out_size) {
    const float* vert = (const float*)d_in[0];
    const float* horiz = (const float*)d_in[1];
    const unsigned char* mask = (const unsigned char*)d_in[2];
    const float* gw1 = (const float*)d_in[3];
    const float* gb1 = (const float*)d_in[4];
    const float* gw2 = (const float*)d_in[5];
    const float* gb2 = (const float*)d_in[6];
    const float* aw1 = (const float*)d_in[7];
    const float* ab1 = (const float*)d_in[8];
    const float* aw2 = (const float*)d_in[9];
    const float* ab2 = (const float*)d_in[10];

    float* out = (float*)d_out;
    float* out_fused = out;                                   // L*B*D
    float* out_pm = out + (size_t)Lq * Bq * Dq;               // L*B*N*D
    float* out_attn = out_pm + (size_t)Lq * Bq * Nq * Dq;     // B*L*N

    prep_kernel<<<(GHq * KC + 255) / 256, 256>>>(gw1, aw1, mask);

    cudaFuncSetAttribute(fusion_main, cudaFuncAttributeMaxDynamicSharedMemorySize, SMEM_TOTAL);
    fusion_main<<<Lq * Bq / 4, THREADS, SMEM_TOTAL>>>(vert, horiz, mask,
                                                      gb1, gw2, gb2, ab1, aw2, ab2,
                                                      out_fused, out_pm, out_attn);
}

// round 4
// speedup vs baseline: 2.4066x; 2.0079x over previous
#include <cuda_runtime.h>
#include <cuda_bf16.h>
#include <cstdint>
#include <math.h>
#include <float.h>

#define Lq 512
#define Bq 8
#define Nq 32
#define Dq 256
#define GHq 128
#define AHq 64
#define KC 512
#define THREADS 256

// Split weights, bf16 hi/lo, layout [n][k] (k contiguous)
__device__ __nv_bfloat16 g_w1hi[GHq * KC];
__device__ __nv_bfloat16 g_w1lo[GHq * KC];
__device__ __nv_bfloat16 g_w2hi[AHq * Dq];
__device__ __nv_bfloat16 g_w2lo[AHq * Dq];
__device__ int g_mask_mode;  // 0 = byte bool, 1 = int32, 2 = float32

__global__ void prep_kernel(const float* __restrict__ gw1, const float* __restrict__ aw1,
                            const unsigned char* __restrict__ mask_raw) {
    int i = blockIdx.x * blockDim.x + threadIdx.x;
    if (i < GHq * KC) {
        float x = gw1[i];
        __nv_bfloat16 h = __float2bfloat16_rn(x);
        g_w1hi[i] = h;
        g_w1lo[i] = __float2bfloat16_rn(x - __bfloat162float(h));
    }
    if (i < AHq * Dq) {
        float x = aw1[i];
        __nv_bfloat16 h = __float2bfloat16_rn(x);
        g_w2hi[i] = h;
        g_w2lo[i] = __float2bfloat16_rn(x - __bfloat162float(h));
    }
    if (blockIdx.x == 0 && threadIdx.x == 0) {
        bool anyFloatSig = false, anyOffNonzero = false;
        for (int j = 0; j < 4096; j++) {
            unsigned char c = mask_raw[j];
            if ((j & 3) != 0) {
                if (c == 0x3Fu || c == 0x80u) anyFloatSig = true;
                if (c != 0) anyOffNonzero = true;
            }
        }
        g_mask_mode = anyFloatSig ? 2 : (anyOffNonzero ? 0 : 1);
    }
}

__device__ __forceinline__ uint32_t smem_u32(const void* p) {
    return (uint32_t)__cvta_generic_to_shared(p);
}
__device__ __forceinline__ void ldmatrix_x4(uint32_t* r, uint32_t addr) {
    asm volatile("ldmatrix.sync.aligned.m8n8.x4.shared.b16 {%0,%1,%2,%3}, [%4];"
                 : "=r"(r[0]), "=r"(r[1]), "=r"(r[2]), "=r"(r[3]) : "r"(addr));
}
__device__ __forceinline__ void mma16816(float* c, const uint32_t* a, uint32_t b0, uint32_t b1) {
    asm volatile("mma.sync.aligned.m16n8k16.row.col.f32.bf16.bf16.f32 "
                 "{%0,%1,%2,%3},{%4,%5,%6,%7},{%8,%9},{%0,%1,%2,%3};"
                 : "+f"(c[0]), "+f"(c[1]), "+f"(c[2]), "+f"(c[3])
                 : "r"(a[0]), "r"(a[1]), "r"(a[2]), "r"(a[3]), "r"(b0), "r"(b1));
}

// SMEM: A tiles [64][72] hi/lo, W tiles [128][72] hi/lo (stride 72 = conflict-free ldmatrix)
#define A_STRIDE 72
#define W_STRIDE 72
#define OFF_AHI 0
#define OFF_ALO (64 * A_STRIDE * 2)
#define OFF_WHI (OFF_ALO + 64 * A_STRIDE * 2)
#define OFF_WLO (OFF_WHI + 128 * W_STRIDE * 2)
#define OFF_GPART (OFF_WLO + 128 * W_STRIDE * 2)   // float [64][4]
#define OFF_GATE (OFF_GPART + 64 * 4 * 4)          // float [64]
#define OFF_ATTN (OFF_GATE + 64 * 4)               // float [64]
#define SMEM_TOTAL (OFF_ATTN + 64 * 4)

__global__ __launch_bounds__(THREADS, 3)
void fusion_main(const float* __restrict__ vert, const float* __restrict__ horiz,
                 const unsigned char* __restrict__ mask,
                 const float* __restrict__ gb1, const float* __restrict__ gw2,
                 const float* __restrict__ gb2,
                 const float* __restrict__ ab1, const float* __restrict__ aw2,
                 const float* __restrict__ ab2,
                 float* __restrict__ out_fused, float* __restrict__ out_pm,
                 float* __restrict__ out_attn) {
    extern __shared__ char smem[];
    __nv_bfloat16* Ahi = (__nv_bfloat16*)(smem + OFF_AHI);
    __nv_bfloat16* Alo = (__nv_bfloat16*)(smem + OFF_ALO);
    __nv_bfloat16* Whi = (__nv_bfloat16*)(smem + OFF_WHI);
    __nv_bfloat16* Wlo = (__nv_bfloat16*)(smem + OFF_WLO);
    float* gpart = (float*)(smem + OFF_GPART);
    float* gate_s = (float*)(smem + OFF_GATE);
    float* attn_s = (float*)(smem + OFF_ATTN);

    const int tid = threadIdx.x;
    const int wid = tid >> 5;
    const int lane = tid & 31;
    const int cta = blockIdx.x;          // 2 lb pairs: lb = cta*2 + lbi

    // GEMM1 warp grid: 2(m) x 4(n); warp tile m32 x n32
    const int mg = wid >> 2;
    const int ng = wid & 3;

    // ldmatrix A addressing (m16 x k16 tile)
    const int lgrp = lane >> 3;
    const int lrow = (lane & 7) + (lgrp & 1) * 8;
    const int lcol = (lgrp >> 1) * 8;
    // ldmatrix B addressing (n16 x k16 tile pair): tiles: [n0..7,k0][n0..7,k8][n8..15,k0][n8..15,k8]
    const int bn_off = ((lane >> 4) & 1) * 8 + (lane & 7);
    const int bk_off = ((lane >> 3) & 1) * 8;

    // ================= GEMM1: C1[64][128] = concat(V,H) @ gw1^T =================
    float acc[2][4][4];
#pragma unroll
    for (int a = 0; a < 2; a++)
#pragma unroll
        for (int b = 0; b < 4; b++)
#pragma unroll
            for (int c = 0; c < 4; c++) acc[a][b][c] = 0.f;

#pragma unroll 1
    for (int chunk = 0; chunk < 8; chunk++) {
        const float* feat = (chunk < 4) ? vert : horiz;
        const int kb = (chunk & 3) * 64;
        __syncthreads();
        // stage A chunk: 64 m x 64 k fp32 -> bf16 hi/lo
        const float4* src = (const float4*)(feat + (size_t)cta * 64 * Dq);
#pragma unroll
        for (int t = 0; t < 4; t++) {
            int j = tid + t * THREADS;           // 0..1023
            int m = j >> 4;
            int kq = (j & 15) * 4;
            float4 v = src[m * (Dq / 4) + (kb + kq) / 4];
            __nv_bfloat16 h0 = __float2bfloat16_rn(v.x), h1 = __float2bfloat16_rn(v.y);
            __nv_bfloat16 h2 = __float2bfloat16_rn(v.z), h3 = __float2bfloat16_rn(v.w);
            __nv_bfloat162* dh = (__nv_bfloat162*)&Ahi[m * A_STRIDE + kq];
            dh[0] = __nv_bfloat162(h0, h1);
            dh[1] = __nv_bfloat162(h2, h3);
            __nv_bfloat162* dl = (__nv_bfloat162*)&Alo[m * A_STRIDE + kq];
            dl[0] = __nv_bfloat162(__float2bfloat16_rn(v.x - __bfloat162float(h0)),
                                   __float2bfloat16_rn(v.y - __bfloat162float(h1)));
            dl[1] = __nv_bfloat162(__float2bfloat16_rn(v.z - __bfloat162float(h2)),
                                   __float2bfloat16_rn(v.w - __bfloat162float(h3)));
        }
        // stage W1 chunk: 128 n x 64 k bf16 hi/lo (uint4 = 8 bf16)
        {
            const uint4* s_hi = (const uint4*)g_w1hi;
            const uint4* s_lo = (const uint4*)g_w1lo;
            uint4* d_hi = (uint4*)Whi;
            uint4* d_lo = (uint4*)Wlo;
#pragma unroll
            for (int t = 0; t < 4; t++) {
                int j = tid + t * THREADS;       // 0..1023 = 128 rows x 8 uint4
                int n = j >> 3;
                int q = j & 7;
                d_hi[n * 9 + q] = s_hi[n * 64 + chunk * 8 + q];
                d_lo[n * 9 + q] = s_lo[n * 64 + chunk * 8 + q];
            }
        }
        __syncthreads();

#pragma unroll
        for (int ks = 0; ks < 4; ks++) {
            const int kk = ks * 16;
            uint32_t ah[2][4], al[2][4];
#pragma unroll
            for (int mt = 0; mt < 2; mt++) {
                int row = mg * 32 + mt * 16 + lrow;
                ldmatrix_x4(ah[mt], smem_u32(&Ahi[row * A_STRIDE + kk + lcol]));
                ldmatrix_x4(al[mt], smem_u32(&Alo[row * A_STRIDE + kk + lcol]));
            }
#pragma unroll
            for (int nh = 0; nh < 2; nh++) {
                uint32_t bh[4], bl[4];
                uint32_t baddr = smem_u32(&Whi[(ng * 32 + nh * 16 + bn_off) * W_STRIDE + kk + bk_off]);
                ldmatrix_x4(bh, baddr);
                uint32_t laddr = smem_u32(&Wlo[(ng * 32 + nh * 16 + bn_off) * W_STRIDE + kk + bk_off]);
                ldmatrix_x4(bl, laddr);
#pragma unroll
                for (int nf2 = 0; nf2 < 2; nf2++) {
                    int nf = nh * 2 + nf2;
#pragma unroll
                    for (int mt = 0; mt < 2; mt++) {
                        mma16816(acc[mt][nf], ah[mt], bh[nf2 * 2], bh[nf2 * 2 + 1]);
                        mma16816(acc[mt][nf], al[mt], bh[nf2 * 2], bh[nf2 * 2 + 1]);
                        mma16816(acc[mt][nf], ah[mt], bl[nf2 * 2], bl[nf2 * 2 + 1]);
                    }
                }
            }
        }
    }

    // ---- gate epilogue: relu(C1+gb1) . gw2 -> partials -> sigmoid ----
    {
        float p0[2] = {0.f, 0.f}, p1[2] = {0.f, 0.f};
#pragma unroll
        for (int nf = 0; nf < 4; nf++) {
#pragma unroll
            for (int j = 0; j < 2; j++) {
                int n = ng * 32 + nf * 8 + 2 * (lane & 3) + j;
                float b1v = __ldg(&gb1[n]);
                float w2v = __ldg(&gw2[n]);
#pragma unroll
                for (int mt = 0; mt < 2; mt++) {
                    p0[mt] += fmaxf(acc[mt][nf][j] + b1v, 0.f) * w2v;
                    p1[mt] += fmaxf(acc[mt][nf][j + 2] + b1v, 0.f) * w2v;
                }
            }
        }
#pragma unroll
        for (int o = 1; o <= 2; o <<= 1) {
#pragma unroll
            for (int mt = 0; mt < 2; mt++) {
                p0[mt] += __shfl_xor_sync(0xffffffffu, p0[mt], o);
                p1[mt] += __shfl_xor_sync(0xffffffffu, p1[mt], o);
            }
        }
        if ((lane & 3) == 0) {
            int r = lane >> 2;
#pragma unroll
            for (int mt = 0; mt < 2; mt++) {
                gpart[(mg * 32 + mt * 16 + r) * 4 + ng] = p0[mt];
                gpart[(mg * 32 + mt * 16 + 8 + r) * 4 + ng] = p1[mt];
            }
        }
        __syncthreads();
        if (tid < 64) {
            float s = gpart[tid * 4] + gpart[tid * 4 + 1] + gpart[tid * 4 + 2] + gpart[tid * 4 + 3];
            s += __ldg(gb2);
            gate_s[tid] = 1.f / (1.f + __expf(-s));
        }
        __syncthreads();
    }

    // ========== blend + GEMM2 (k-chunked through the A buffers) ==========
    const int ng2 = wid & 3;          // n0 = ng2*16
    const int mg2 = wid >> 2;
    float acc2[2][2][4];
#pragma unroll
    for (int a = 0; a < 2; a++)
#pragma unroll
        for (int b = 0; b < 2; b++)
#pragma unroll
            for (int c = 0; c < 4; c++) acc2[a][b][c] = 0.f;

#pragma unroll 1
    for (int kc = 0; kc < 4; kc++) {
        __syncthreads();
        // blend chunk: p = g*v + (1-g)*h; write pm fp32; stage hi/lo
        {
            const float4* v4 = (const float4*)(vert + (size_t)cta * 64 * Dq);
            const float4* h4 = (const float4*)(horiz + (size_t)cta * 64 * Dq);
            float4* pm4 = (float4*)(out_pm + (size_t)cta * 64 * Dq);
#pragma unroll
            for (int t = 0; t < 4; t++) {
                int j = tid + t * THREADS;       // 0..1023
                int m = j >> 4;
                int kq = (j & 15) * 4;
                int gi = m * (Dq / 4) + (kc * 64 + kq) / 4;
                float g = gate_s[m];
                float og = 1.f - g;
                float4 v = v4[gi];
                float4 h = h4[gi];
                float4 p;
                p.x = fmaf(g, v.x, og * h.x);
                p.y = fmaf(g, v.y, og * h.y);
                p.z = fmaf(g, v.z, og * h.z);
                p.w = fmaf(g, v.w, og * h.w);
                pm4[gi] = p;
                __nv_bfloat16 h0 = __float2bfloat16_rn(p.x), h1 = __float2bfloat16_rn(p.y);
                __nv_bfloat16 h2 = __float2bfloat16_rn(p.z), h3 = __float2bfloat16_rn(p.w);
                __nv_bfloat162* dh = (__nv_bfloat162*)&Ahi[m * A_STRIDE + kq];
                dh[0] = __nv_bfloat162(h0, h1);
                dh[1] = __nv_bfloat162(h2, h3);
                __nv_bfloat162* dl = (__nv_bfloat162*)&Alo[m * A_STRIDE + kq];
                dl[0] = __nv_bfloat162(__float2bfloat16_rn(p.x - __bfloat162float(h0)),
                                       __float2bfloat16_rn(p.y - __bfloat162float(h1)));
                dl[1] = __nv_bfloat162(__float2bfloat16_rn(p.z - __bfloat162float(h2)),
                                       __float2bfloat16_rn(p.w - __bfloat162float(h3)));
            }
        }
        // stage W2 chunk: 64 n x 64 k
        {
            const uint4* s_hi = (const uint4*)g_w2hi;
            const uint4* s_lo = (const uint4*)g_w2lo;
            uint4* d_hi = (uint4*)Whi;
            uint4* d_lo = (uint4*)Wlo;
#pragma unroll
            for (int t = 0; t < 2; t++) {
                int j = tid + t * THREADS;       // 0..511 = 64 rows x 8 uint4
                int n = j >> 3;
                int q = j & 7;
                d_hi[n * 9 + q] = s_hi[n * 32 + kc * 8 + q];
                d_lo[n * 9 + q] = s_lo[n * 32 + kc * 8 + q];
            }
        }
        __syncthreads();

#pragma unroll
        for (int ks = 0; ks < 4; ks++) {
            const int kk = ks * 16;
            uint32_t ah[2][4], al[2][4];
#pragma unroll
            for (int mt = 0; mt < 2; mt++) {
                int row = mg2 * 32 + mt * 16 + lrow;
                ldmatrix_x4(ah[mt], smem_u32(&Ahi[row * A_STRIDE + kk + lcol]));
                ldmatrix_x4(al[mt], smem_u32(&Alo[row * A_STRIDE + kk + lcol]));
            }
            uint32_t bh[4], bl[4];
            ldmatrix_x4(bh, smem_u32(&Whi[(ng2 * 16 + bn_off) * W_STRIDE + kk + bk_off]));
            ldmatrix_x4(bl, smem_u32(&Wlo[(ng2 * 16 + bn_off) * W_STRIDE + kk + bk_off]));
#pragma unroll
            for (int nf = 0; nf < 2; nf++) {
#pragma unroll
                for (int mt = 0; mt < 2; mt++) {
                    mma16816(acc2[mt][nf], ah[mt], bh[nf * 2], bh[nf * 2 + 1]);
                    mma16816(acc2[mt][nf], al[mt], bh[nf * 2], bh[nf * 2 + 1]);
                    mma16816(acc2[mt][nf], ah[mt], bl[nf * 2], bl[nf * 2 + 1]);
                }
            }
        }
    }

    // ---- logits epilogue: tanh(C2+ab1) . aw2 ----
    {
        float p0[2] = {0.f, 0.f}, p1[2] = {0.f, 0.f};
#pragma unroll
        for (int nf = 0; nf < 2; nf++) {
#pragma unroll
            for (int j = 0; j < 2; j++) {
                int n = ng2 * 16 + nf * 8 + 2 * (lane & 3) + j;
                float b1v = __ldg(&ab1[n]);
                float w2v = __ldg(&aw2[n]);
#pragma unroll
                for (int mt = 0; mt < 2; mt++) {
                    p0[mt] += tanhf(acc2[mt][nf][j] + b1v) * w2v;
                    p1[mt] += tanhf(acc2[mt][nf][j + 2] + b1v) * w2v;
                }
            }
        }
#pragma unroll
        for (int o = 1; o <= 2; o <<= 1) {
#pragma unroll
            for (int mt = 0; mt < 2; mt++) {
                p0[mt] += __shfl_xor_sync(0xffffffffu, p0[mt], o);
                p1[mt] += __shfl_xor_sync(0xffffffffu, p1[mt], o);
            }
        }
        __syncthreads();  // gpart reuse
        if ((lane & 3) == 0) {
            int r = lane >> 2;
#pragma unroll
            for (int mt = 0; mt < 2; mt++) {
                gpart[(mg2 * 32 + mt * 16 + r) * 4 + ng2] = p0[mt];
                gpart[(mg2 * 32 + mt * 16 + 8 + r) * 4 + ng2] = p1[mt];
            }
        }
        __syncthreads();
    }

    // ---- masked softmax per lb (2 warps; lane = msg) ----
    if (tid < 64) {
        int lbi = tid >> 5;
        int msg = tid & 31;
        int lb = cta * 2 + lbi;
        int l = lb >> 3, b = lb & 7;
        float lg = gpart[tid * 4] + gpart[tid * 4 + 1] + gpart[tid * 4 + 2] + gpart[tid * 4 + 3];
        lg += __ldg(ab2);
        size_t midx = ((size_t)b * Nq + msg) * Lq + l;
        int mode = g_mask_mode;
        bool valid;
        if (mode == 2)      valid = ((const float*)mask)[midx] != 0.0f;
        else if (mode == 1) valid = ((const int*)mask)[midx] != 0;
        else                valid = mask[midx] != 0;
        float mv = valid ? lg : -FLT_MAX;
#pragma unroll
        for (int o = 16; o >= 1; o >>= 1)
            mv = fmaxf(mv, __shfl_xor_sync(0xffffffffu, mv, o));
        float e = valid ? __expf(lg - mv) : 0.f;
        float s = e;
#pragma unroll
        for (int o = 16; o >= 1; o >>= 1)
            s += __shfl_xor_sync(0xffffffffu, s, o);
        float a = (s > 0.f) ? e / s : 0.f;
        attn_s[tid] = a;
        out_attn[((size_t)b * Lq + l) * Nq + msg] = a;
    }
    __syncthreads();

    // ---- fused[lb][d] = sum_m attn * per_msg (re-read pm from L2) ----
#pragma unroll
    for (int t = 0; t < 2; t++) {
        int j = tid + t * THREADS;          // 0..511 = 2 lb x 256 d
        int lbi = j >> 8;
        int d = j & 255;
        const float* pmr = out_pm + (size_t)cta * 64 * Dq + (size_t)lbi * 32 * Dq + d;
        float f = 0.f;
#pragma unroll
        for (int m = 0; m < Nq; m++)
            f = fmaf(attn_s[lbi * 32 + m], pmr[m * Dq], f);
        out_fused[(size_t)cta * 512 + j] = f;
    }
}

extern "C" void kernel_launch(void* const* d_in, const int* in_sizes, int n_in,
                              void* d_out, int out_size) {
    const float* vert = (const float*)d_in[0];
    const float* horiz = (const float*)d_in[1];
    const unsigned char* mask = (const unsigned char*)d_in[2];
    const float* gw1 = (const float*)d_in[3];
    const float* gb1 = (const float*)d_in[4];
    const float* gw2 = (const float*)d_in[5];
    const float* gb2 = (const float*)d_in[6];
    const float* aw1 = (const float*)d_in[7];
    const float* ab1 = (const float*)d_in[8];
    const float* aw2 = (const float*)d_in[9];
    const float* ab2 = (const float*)d_in[10];

    float* out = (float*)d_out;
    float* out_fused = out;                                   // L*B*D
    float* out_pm = out + (size_t)Lq * Bq * Dq;               // L*B*N*D
    float* out_attn = out_pm + (size_t)Lq * Bq * Nq * Dq;     // B*L*N

    prep_kernel<<<(GHq * KC + 255) / 256, 256>>>(gw1, aw1, mask);

    cudaFuncSetAttribute(fusion_main, cudaFuncAttributeMaxDynamicSharedMemorySize, SMEM_TOTAL);
    fusion_main<<<Lq * Bq / 2, THREADS, SMEM_TOTAL>>>(vert, horiz, mask,
                                                      gb1, gw2, gb2, ab1, aw2, ab2,
                                                      out_fused, out_pm, out_attn);
}